// round 2
// baseline (speedup 1.0000x reference)
#include <cuda_runtime.h>
#include <cstdint>
#include <cstddef>

// Wigner D matrices per quaternion: D1 = 3x3 (l=1), D2 = 5x5 (l=2).
__device__ float g_D1[16 * 9];
__device__ float g_D2[16 * 25];

// Build z-rotation matrix of size d=2l+1.
// Reference order: set sin on anti-diagonal, then cos on diagonal (center -> cos).
__device__ void zrot(float ang, int d, float* M) {
    int l = (d - 1) / 2;
    for (int x = 0; x < d * d; x++) M[x] = 0.0f;
    for (int idx = 0; idx < d; idx++) {
        float fr = (float)(l - idx);
        M[idx * d + (d - 1 - idx)] = sinf(fr * ang);
        M[idx * d + idx]           = cosf(fr * ang);   // overwrites center (cos(0)=1)
    }
}

__device__ void matmul_sq(const float* A, const float* B, float* C, int d) {
    for (int i = 0; i < d; i++)
        for (int j = 0; j < d; j++) {
            float s = 0.0f;
            for (int k = 0; k < d; k++) s = fmaf(A[i * d + k], B[k * d + j], s);
            C[i * d + j] = s;
        }
}

// One thread per quaternion: quat -> (alpha,beta,gamma) -> D_l = Za @ J @ Zb @ J @ Zg
__global__ void setup_kernel(const float* __restrict__ q,
                             const float* __restrict__ J1,
                             const float* __restrict__ J2,
                             int T) {
    int t = threadIdx.x;
    if (t >= T) return;

    float r = q[4 * t + 0], i = q[4 * t + 1], j = q[4 * t + 2], k = q[4 * t + 3];
    float inv = rsqrtf(r * r + i * i + j * j + k * k);
    r *= inv; i *= inv; j *= inv; k *= inv;
    float two_s = 2.0f / (r * r + i * i + j * j + k * k);

    float M01 = two_s * (i * j - k * r);
    float M21 = two_s * (j * k + i * r);
    float M11 = 1.0f - two_s * (i * i + k * k);
    float M10 = two_s * (i * j + k * r);
    float M12 = two_s * (j * k - i * r);

    float alpha = atan2f(M01, M21);
    float beta  = acosf(fmaxf(-1.0f, fminf(1.0f, M11)));
    float gamma = atan2f(M10, -M12);

    // l = 1 (3x3)
    {
        float Za[9], Zb[9], Zg[9], t1[9], t2[9];
        zrot(alpha, 3, Za); zrot(beta, 3, Zb); zrot(gamma, 3, Zg);
        matmul_sq(Za, J1, t1, 3);
        matmul_sq(t1, Zb, t2, 3);
        matmul_sq(t2, J1, t1, 3);
        matmul_sq(t1, Zg, &g_D1[t * 9], 3);
    }
    // l = 2 (5x5)
    {
        float Za[25], Zb[25], Zg[25], t1[25], t2[25];
        zrot(alpha, 5, Za); zrot(beta, 5, Zb); zrot(gamma, 5, Zg);
        matmul_sq(Za, J2, t1, 5);
        matmul_sq(t1, Zb, t2, 5);
        matmul_sq(t2, J2, t1, 5);
        matmul_sq(t1, Zg, &g_D2[t * 25], 5);
    }
}

// One block per point p. 128 threads:
//   tid 0..31  : l=0 block, hold float4 of channels [4*tid, 4*tid+3], store directly.
//   tid 32..95 : l=1, m = tid-32, input channels 128 + 3m .. +2
//   tid 96..127: l=2, m = tid-96, input channels 320 + 5m .. +4
// Transformed l1/l2 outputs staged in double-buffered smem (odd stride ->
// conflict-free STS), then copied out coalesced as float4. One barrier per
// t-iteration: the barrier at iter t+1 protects buffer (t&1) from being
// overwritten at iter t+2, since every thread passes it only after finishing
// its iter-t copy.
__global__ __launch_bounds__(128) void transform_kernel(
        const float* __restrict__ feat,
        float* __restrict__ out,
        int N, int T) {
    __shared__ float sD1[16 * 9];
    __shared__ float sD2[16 * 25];
    __shared__ float sOut[2][352];   // channels 128..479, double-buffered

    const int tid = threadIdx.x;
    const int p = blockIdx.x;

    for (int x = tid; x < T * 9; x += 128) sD1[x] = g_D1[x];
    for (int x = tid; x < T * 25; x += 128) sD2[x] = g_D2[x];

    const float* fr = feat + (size_t)p * 480;

    float4 f0 = make_float4(0.f, 0.f, 0.f, 0.f);
    float fl1_0 = 0.f, fl1_1 = 0.f, fl1_2 = 0.f;
    float fl2[5] = {0.f, 0.f, 0.f, 0.f, 0.f};

    if (tid < 32) {
        f0 = reinterpret_cast<const float4*>(fr)[tid];
    } else if (tid < 96) {
        const float* src = fr + 128 + (tid - 32) * 3;
        fl1_0 = src[0]; fl1_1 = src[1]; fl1_2 = src[2];
    } else {
        const float* src = fr + 320 + (tid - 96) * 5;
#pragma unroll
        for (int b = 0; b < 5; b++) fl2[b] = src[b];
    }

    __syncthreads();

    for (int t = 0; t < T; t++) {
        float* ob = out + ((size_t)t * N + p) * 480;
        float* buf = sOut[t & 1];

        if (tid < 32) {
            reinterpret_cast<float4*>(ob)[tid] = f0;
        } else if (tid < 96) {
            const int m = tid - 32;
            const float* D = sD1 + t * 9;
#pragma unroll
            for (int a = 0; a < 3; a++) {
                float v = fmaf(D[a * 3 + 0], fl1_0,
                          fmaf(D[a * 3 + 1], fl1_1,
                               D[a * 3 + 2] * fl1_2));
                buf[m * 3 + a] = v;
            }
        } else {
            const int m = tid - 96;
            const float* D = sD2 + t * 25;
#pragma unroll
            for (int a = 0; a < 5; a++) {
                float v = 0.0f;
#pragma unroll
                for (int b = 0; b < 5; b++) v = fmaf(D[a * 5 + b], fl2[b], v);
                buf[192 + m * 5 + a] = v;
            }
        }

        __syncthreads();

        // Coalesced copy of staged channels 128..479 (352 floats = 88 float4)
        if (tid >= 32 && tid < 120) {
            const int c4 = tid - 32;
            float4 v = reinterpret_cast<const float4*>(buf)[c4];
            reinterpret_cast<float4*>(ob + 128)[c4] = v;
        }
    }
}

extern "C" void kernel_launch(void* const* d_in, const int* in_sizes, int n_in,
                              void* d_out, int out_size) {
    const float* feat = (const float*)d_in[0];
    const float* q    = (const float*)d_in[1];
    // d_in[2] = J0 (unused: l=0 is a pure broadcast in the reference)
    const float* J1   = (const float*)d_in[3];
    const float* J2   = (const float*)d_in[4];
    float* out = (float*)d_out;

    const int T = in_sizes[1] / 4;     // 16
    const int N = in_sizes[0] / 480;   // 16384

    setup_kernel<<<1, 32>>>(q, J1, J2, T);
    transform_kernel<<<N, 128>>>(feat, out, N, T);
}